// round 14
// baseline (speedup 1.0000x reference)
#include <cuda_runtime.h>
#include <cstddef>
#include <cstdint>
#include <math_constants.h>

#define B_DIM 4096
#define K_DIM 64
#define D_DIM 512
#define N_AGENTS 64
#define NEG_INF -1e9f
#define THREADS 256
#define NWARP 8
#define GRID 296
#define NBUF 5
#define CROWS 8
#define CBYTES (CROWS * D_DIM * 4)            // 16 KB
#define CFLOATS (CROWS * D_DIM)
#define STAGE_OFF (NBUF * CBYTES)             // 81920
#define MBAR_OFF (STAGE_OFF + NWARP * D_DIM * 4)  // 98304
#define SMEM_TOTAL (MBAR_OFF + 64)

__device__ __forceinline__ uint32_t smem_u32(const void* p) {
    return (uint32_t)__cvta_generic_to_shared(p);
}
__device__ __forceinline__ void mbar_init(uint32_t a, uint32_t cnt) {
    asm volatile("mbarrier.init.shared.b64 [%0], %1;" :: "r"(a), "r"(cnt) : "memory");
}
__device__ __forceinline__ void mbar_expect_tx(uint32_t a, uint32_t bytes) {
    asm volatile("mbarrier.arrive.expect_tx.shared.b64 _, [%0], %1;" :: "r"(a), "r"(bytes) : "memory");
}
__device__ __forceinline__ void mbar_wait(uint32_t a, uint32_t parity) {
    while (true) {
        uint32_t done;
        asm volatile(
            "{\n\t.reg .pred p;\n\t"
            "mbarrier.try_wait.parity.acquire.cta.shared::cta.b64 p, [%1], %2, 0x989680;\n\t"
            "selp.b32 %0, 1, 0, p;\n\t}"
            : "=r"(done) : "r"(a), "r"(parity) : "memory");
        if (done) break;
    }
}
__device__ __forceinline__ void bulk_copy(uint32_t dst, const void* src, uint32_t bytes, uint32_t mbar) {
    asm volatile(
        "cp.async.bulk.shared::cluster.global.mbarrier::complete_tx::bytes [%0], [%1], %2, [%3];"
        :: "r"(dst), "l"(src), "r"(bytes), "r"(mbar) : "memory");
}

__global__ __launch_bounds__(THREADS, 2)
void block_diag_agg_kernel(const float* __restrict__ h,
                           const float* __restrict__ keys,
                           const int* __restrict__ sigma,
                           float* __restrict__ out) {
    extern __shared__ __align__(128) char smem[];
    __shared__ float s_m[NWARP];
    __shared__ float s_s[NWARP];
    __shared__ float s_fac[NWARP];

    const int tid  = threadIdx.x;
    const int warp = tid >> 5;
    const int lane = tid & 31;
    const int bid  = blockIdx.x;

    const uint32_t sb32     = smem_u32(smem);
    const uint32_t full_bar = sb32 + MBAR_OFF;    // NBUF x 8 B

    const int ntiles = (B_DIM - bid + GRID - 1) / GRID;   // >= 13
    const int total  = ntiles * 8;                         // chunk stream length

    if (tid == 0) {
        #pragma unroll
        for (int s = 0; s < NBUF; s++) mbar_init(full_bar + s * 8, 1);
    }
    __syncthreads();

    // ---- Prologue: queue the first NBUF chunks (all in tile 0) ----
    if (tid == 0) {
        #pragma unroll
        for (int g = 0; g < NBUF; g++) {
            const float* src = h + (size_t)bid * (K_DIM * D_DIM) + g * CFLOATS;
            mbar_expect_tx(full_bar + g * 8, CBYTES);
            bulk_copy(sb32 + g * CBYTES, src, CBYTES, full_bar + g * 8);
        }
    }

    float* stage = (float*)(smem + STAGE_OFF);
    int buf = 0, parity = 0;                 // rolling ring cursor (g mod NBUF)

    for (int t = 0; t < ntiles; t++) {
        const int b   = bid + t * GRID;
        const int* sg = sigma + (size_t)b * K_DIM;

        float m = -CUDART_INF_F;
        float s = 0.0f;
        float4 acc0 = make_float4(0.f, 0.f, 0.f, 0.f);
        float4 acc1 = make_float4(0.f, 0.f, 0.f, 0.f);
        float4 acc2 = make_float4(0.f, 0.f, 0.f, 0.f);
        float4 acc3 = make_float4(0.f, 0.f, 0.f, 0.f);

        #pragma unroll
        for (int c = 0; c < 8; c++) {
            const int g = t * 8 + c;
            mbar_wait(full_bar + buf * 8, parity);

            // warp w consumes row w of this chunk: global slot k = 8c + w
            const int k = c * CROWS + warp;
            const int sid    = __ldg(&sg[k]);
            const bool valid = (sid < N_AGENTS);
            const float4* hrow = (const float4*)(smem + buf * CBYTES + warp * (D_DIM * 4));
            const float4* krow = (const float4*)(keys + (size_t)(valid ? sid : 0) * D_DIM);

            float4 hv0 = hrow[lane +  0];
            float4 hv1 = hrow[lane + 32];
            float4 hv2 = hrow[lane + 64];
            float4 hv3 = hrow[lane + 96];
            float4 kv0 = __ldg(&krow[lane +  0]);
            float4 kv1 = __ldg(&krow[lane + 32]);
            float4 kv2 = __ldg(&krow[lane + 64]);
            float4 kv3 = __ldg(&krow[lane + 96]);

            float dot = 0.0f;
            dot = fmaf(hv0.x, kv0.x, dot); dot = fmaf(hv0.y, kv0.y, dot);
            dot = fmaf(hv0.z, kv0.z, dot); dot = fmaf(hv0.w, kv0.w, dot);
            dot = fmaf(hv1.x, kv1.x, dot); dot = fmaf(hv1.y, kv1.y, dot);
            dot = fmaf(hv1.z, kv1.z, dot); dot = fmaf(hv1.w, kv1.w, dot);
            dot = fmaf(hv2.x, kv2.x, dot); dot = fmaf(hv2.y, kv2.y, dot);
            dot = fmaf(hv2.z, kv2.z, dot); dot = fmaf(hv2.w, kv2.w, dot);
            dot = fmaf(hv3.x, kv3.x, dot); dot = fmaf(hv3.y, kv3.y, dot);
            dot = fmaf(hv3.z, kv3.z, dot); dot = fmaf(hv3.w, kv3.w, dot);

            #pragma unroll
            for (int off = 16; off > 0; off >>= 1)
                dot += __shfl_xor_sync(0xFFFFFFFFu, dot, off);

            const float logit = valid ? dot : NEG_INF;
            const float m_new = fmaxf(m, logit);
            const float scale = __expf(m - m_new);     // iter 0: exp(-inf)=0
            const float pw    = __expf(logit - m_new);
            s = fmaf(s, scale, pw);
            m = m_new;

            acc0.x = fmaf(acc0.x, scale, pw * hv0.x);
            acc0.y = fmaf(acc0.y, scale, pw * hv0.y);
            acc0.z = fmaf(acc0.z, scale, pw * hv0.z);
            acc0.w = fmaf(acc0.w, scale, pw * hv0.w);
            acc1.x = fmaf(acc1.x, scale, pw * hv1.x);
            acc1.y = fmaf(acc1.y, scale, pw * hv1.y);
            acc1.z = fmaf(acc1.z, scale, pw * hv1.z);
            acc1.w = fmaf(acc1.w, scale, pw * hv1.w);
            acc2.x = fmaf(acc2.x, scale, pw * hv2.x);
            acc2.y = fmaf(acc2.y, scale, pw * hv2.y);
            acc2.z = fmaf(acc2.z, scale, pw * hv2.z);
            acc2.w = fmaf(acc2.w, scale, pw * hv2.w);
            acc3.x = fmaf(acc3.x, scale, pw * hv3.x);
            acc3.y = fmaf(acc3.y, scale, pw * hv3.y);
            acc3.z = fmaf(acc3.z, scale, pw * hv3.z);
            acc3.w = fmaf(acc3.w, scale, pw * hv3.w);

            __syncthreads();   // all warps done with this buffer

            // repost this buffer with chunk g+NBUF
            if (tid == 0 && g + NBUF < total) {
                const int gn = g + NBUF, tn = gn >> 3, cn = gn & 7;
                const float* src = h + (size_t)(bid + tn * GRID) * (K_DIM * D_DIM) + cn * CFLOATS;
                mbar_expect_tx(full_bar + buf * 8, CBYTES);
                bulk_copy(sb32 + buf * CBYTES, src, CBYTES, full_bar + buf * 8);
            }

            if (++buf == NBUF) { buf = 0; parity ^= 1; }
        }

        // ---- Epilogue (engine keeps streaming next tile's queued chunks) ----
        if (lane == 0) { s_m[warp] = m; s_s[warp] = s; }
        __syncthreads();

        if (warp == 0) {
            float mw = (lane < NWARP) ? s_m[lane] : -CUDART_INF_F;
            float sw = (lane < NWARP) ? s_s[lane] : 0.0f;
            float mg = mw;
            #pragma unroll
            for (int off = 16; off > 0; off >>= 1)
                mg = fmaxf(mg, __shfl_xor_sync(0xFFFFFFFFu, mg, off));
            float e = __expf(mw - mg);                 // inactive lanes: 0
            float S = e * sw;
            #pragma unroll
            for (int off = 16; off > 0; off >>= 1)
                S += __shfl_xor_sync(0xFFFFFFFFu, S, off);
            if (lane < NWARP) s_fac[lane] = e / S;
        }
        __syncthreads();

        const float f = s_fac[warp];
        float4* stp = (float4*)(stage + warp * D_DIM);
        stp[lane +  0] = make_float4(acc0.x * f, acc0.y * f, acc0.z * f, acc0.w * f);
        stp[lane + 32] = make_float4(acc1.x * f, acc1.y * f, acc1.z * f, acc1.w * f);
        stp[lane + 64] = make_float4(acc2.x * f, acc2.y * f, acc2.z * f, acc2.w * f);
        stp[lane + 96] = make_float4(acc3.x * f, acc3.y * f, acc3.z * f, acc3.w * f);
        __syncthreads();

        float v0 = 0.0f, v1 = 0.0f;
        #pragma unroll
        for (int w = 0; w < NWARP; w++) {
            v0 += stage[w * D_DIM + tid];
            v1 += stage[w * D_DIM + tid + 256];
        }
        out[(size_t)b * D_DIM + tid]       = v0;
        out[(size_t)b * D_DIM + tid + 256] = v1;

        __syncthreads();   // protect stage/s_m/s_s before next tile reuses them
    }
}

extern "C" void kernel_launch(void* const* d_in, const int* in_sizes, int n_in,
                              void* d_out, int out_size) {
    const float* h     = (const float*)d_in[0];
    const float* keys  = (const float*)d_in[1];
    const int*   sigma = (const int*)d_in[2];
    float*       out   = (float*)d_out;

    cudaFuncSetAttribute(block_diag_agg_kernel,
                         cudaFuncAttributeMaxDynamicSharedMemorySize, SMEM_TOTAL);
    block_diag_agg_kernel<<<GRID, THREADS, SMEM_TOTAL>>>(h, keys, sigma, out);
}

// round 15
// speedup vs baseline: 1.0896x; 1.0896x over previous
#include <cuda_runtime.h>
#include <cstddef>
#include <cstdint>
#include <math_constants.h>

#define B_DIM 4096
#define K_DIM 64
#define D_DIM 512
#define N_AGENTS 64
#define NEG_INF -1e9f
#define THREADS 256
#define NWARP 8
#define GRID 296
#define NSLOT 4
#define ROWB (D_DIM * 4)                       // 2 KB per row
#define RING_BYTES (NWARP * NSLOT * ROWB)      // 64 KB
#define STAGE_OFF RING_BYTES                   // 65536
#define MBAR_OFF (STAGE_OFF + NWARP * D_DIM * 4)   // 81920
#define SMEM_TOTAL (MBAR_OFF + NWARP * NSLOT * 8 + 64)

__device__ __forceinline__ uint32_t smem_u32(const void* p) {
    return (uint32_t)__cvta_generic_to_shared(p);
}
__device__ __forceinline__ void mbar_init(uint32_t a, uint32_t cnt) {
    asm volatile("mbarrier.init.shared.b64 [%0], %1;" :: "r"(a), "r"(cnt) : "memory");
}
__device__ __forceinline__ void mbar_expect_tx(uint32_t a, uint32_t bytes) {
    asm volatile("mbarrier.arrive.expect_tx.shared.b64 _, [%0], %1;" :: "r"(a), "r"(bytes) : "memory");
}
__device__ __forceinline__ void mbar_wait(uint32_t a, uint32_t parity) {
    while (true) {
        uint32_t done;
        asm volatile(
            "{\n\t.reg .pred p;\n\t"
            "mbarrier.try_wait.parity.acquire.cta.shared::cta.b64 p, [%1], %2, 0x989680;\n\t"
            "selp.b32 %0, 1, 0, p;\n\t}"
            : "=r"(done) : "r"(a), "r"(parity) : "memory");
        if (done) break;
    }
}
__device__ __forceinline__ void bulk_copy(uint32_t dst, const void* src, uint32_t bytes, uint32_t mbar) {
    asm volatile(
        "cp.async.bulk.shared::cluster.global.mbarrier::complete_tx::bytes [%0], [%1], %2, [%3];"
        :: "r"(dst), "l"(src), "r"(bytes), "r"(mbar) : "memory");
}

__global__ __launch_bounds__(THREADS, 2)
void block_diag_agg_kernel(const float* __restrict__ h,
                           const float* __restrict__ keys,
                           const int* __restrict__ sigma,
                           float* __restrict__ out) {
    extern __shared__ __align__(128) char smem[];
    __shared__ float s_m[NWARP];
    __shared__ float s_s[NWARP];
    __shared__ float s_fac[NWARP];

    const int tid  = threadIdx.x;
    const int warp = tid >> 5;
    const int lane = tid & 31;
    const int bid  = blockIdx.x;

    const uint32_t sb32 = smem_u32(smem);
    // warp w's ring slot s: data at sb32 + (w*NSLOT+s)*ROWB, mbar at wbar + s*8
    const uint32_t wring = sb32 + (uint32_t)(warp * NSLOT) * ROWB;
    const uint32_t wbar  = sb32 + MBAR_OFF + (uint32_t)(warp * NSLOT) * 8;

    const int ntiles = (B_DIM - bid + GRID - 1) / GRID;   // >= 13
    const int total  = ntiles * 8;                        // per-warp row stream length

    if (tid == 0) {
        for (int i = 0; i < NWARP * NSLOT; i++)
            mbar_init(sb32 + MBAR_OFF + i * 8, 1);
    }
    __syncthreads();

    // ---- Prologue: each warp queues its first NSLOT rows (tile 0, rows i*8+w) ----
    if (lane == 0) {
        #pragma unroll
        for (int i = 0; i < NSLOT; i++) {
            const float* src = h + (size_t)bid * (K_DIM * D_DIM) + (size_t)(i * NWARP + warp) * D_DIM;
            mbar_expect_tx(wbar + i * 8, ROWB);
            bulk_copy(wring + i * ROWB, src, ROWB, wbar + i * 8);
        }
    }
    __syncwarp();

    float* stage = (float*)(smem + STAGE_OFF);

    for (int t = 0; t < ntiles; t++) {
        const int b   = bid + t * GRID;
        const int* sg = sigma + (size_t)b * K_DIM;

        float m = -CUDART_INF_F;
        float s = 0.0f;
        float4 acc0 = make_float4(0.f, 0.f, 0.f, 0.f);
        float4 acc1 = make_float4(0.f, 0.f, 0.f, 0.f);
        float4 acc2 = make_float4(0.f, 0.f, 0.f, 0.f);
        float4 acc3 = make_float4(0.f, 0.f, 0.f, 0.f);

        // ---- Mainloop: 8 rows per warp, private ring, NO CTA barriers ----
        #pragma unroll
        for (int i = 0; i < 8; i++) {
            const int slot = i & 3;
            const uint32_t par = (i >> 2) & 1;    // phase = 2t + (i>>2); parity = (i>>2)&1
            mbar_wait(wbar + slot * 8, par);

            const int k = i * NWARP + warp;       // this warp's row in tile t
            const int sid    = __ldg(&sg[k]);
            const bool valid = (sid < N_AGENTS);
            const float4* hrow = (const float4*)(smem + (size_t)(warp * NSLOT + slot) * ROWB);
            const float4* krow = (const float4*)(keys + (size_t)(valid ? sid : 0) * D_DIM);

            float4 hv0 = hrow[lane +  0];
            float4 hv1 = hrow[lane + 32];
            float4 hv2 = hrow[lane + 64];
            float4 hv3 = hrow[lane + 96];
            float4 kv0 = __ldg(&krow[lane +  0]);
            float4 kv1 = __ldg(&krow[lane + 32]);
            float4 kv2 = __ldg(&krow[lane + 64]);
            float4 kv3 = __ldg(&krow[lane + 96]);

            float dot = 0.0f;
            dot = fmaf(hv0.x, kv0.x, dot); dot = fmaf(hv0.y, kv0.y, dot);
            dot = fmaf(hv0.z, kv0.z, dot); dot = fmaf(hv0.w, kv0.w, dot);
            dot = fmaf(hv1.x, kv1.x, dot); dot = fmaf(hv1.y, kv1.y, dot);
            dot = fmaf(hv1.z, kv1.z, dot); dot = fmaf(hv1.w, kv1.w, dot);
            dot = fmaf(hv2.x, kv2.x, dot); dot = fmaf(hv2.y, kv2.y, dot);
            dot = fmaf(hv2.z, kv2.z, dot); dot = fmaf(hv2.w, kv2.w, dot);
            dot = fmaf(hv3.x, kv3.x, dot); dot = fmaf(hv3.y, kv3.y, dot);
            dot = fmaf(hv3.z, kv3.z, dot); dot = fmaf(hv3.w, kv3.w, dot);

            #pragma unroll
            for (int off = 16; off > 0; off >>= 1)
                dot += __shfl_xor_sync(0xFFFFFFFFu, dot, off);

            const float logit = valid ? dot : NEG_INF;
            const float m_new = fmaxf(m, logit);
            const float scale = __expf(m - m_new);     // iter 0: exp(-inf)=0
            const float pw    = __expf(logit - m_new);
            s = fmaf(s, scale, pw);
            m = m_new;

            acc0.x = fmaf(acc0.x, scale, pw * hv0.x);
            acc0.y = fmaf(acc0.y, scale, pw * hv0.y);
            acc0.z = fmaf(acc0.z, scale, pw * hv0.z);
            acc0.w = fmaf(acc0.w, scale, pw * hv0.w);
            acc1.x = fmaf(acc1.x, scale, pw * hv1.x);
            acc1.y = fmaf(acc1.y, scale, pw * hv1.y);
            acc1.z = fmaf(acc1.z, scale, pw * hv1.z);
            acc1.w = fmaf(acc1.w, scale, pw * hv1.w);
            acc2.x = fmaf(acc2.x, scale, pw * hv2.x);
            acc2.y = fmaf(acc2.y, scale, pw * hv2.y);
            acc2.z = fmaf(acc2.z, scale, pw * hv2.z);
            acc2.w = fmaf(acc2.w, scale, pw * hv2.w);
            acc3.x = fmaf(acc3.x, scale, pw * hv3.x);
            acc3.y = fmaf(acc3.y, scale, pw * hv3.y);
            acc3.z = fmaf(acc3.z, scale, pw * hv3.z);
            acc3.w = fmaf(acc3.w, scale, pw * hv3.w);

            __syncwarp();       // whole warp done reading this slot

            // repost this slot with the row NSLOT steps ahead in this warp's stream
            const int g = t * 8 + i;
            if (lane == 0 && g + NSLOT < total) {
                const int gn = g + NSLOT, tn = gn >> 3, in = gn & 7;
                const float* src = h + (size_t)(bid + tn * GRID) * (K_DIM * D_DIM)
                                     + (size_t)(in * NWARP + warp) * D_DIM;
                mbar_expect_tx(wbar + slot * 8, ROWB);
                bulk_copy(wring + slot * ROWB, src, ROWB, wbar + slot * 8);
            }
        }

        // ---- Epilogue: merge 8 per-warp states (CTA-wide, 3 barriers) ----
        if (lane == 0) { s_m[warp] = m; s_s[warp] = s; }
        __syncthreads();

        if (warp == 0) {
            float mw = (lane < NWARP) ? s_m[lane] : -CUDART_INF_F;
            float sw = (lane < NWARP) ? s_s[lane] : 0.0f;
            float mg = mw;
            #pragma unroll
            for (int off = 16; off > 0; off >>= 1)
                mg = fmaxf(mg, __shfl_xor_sync(0xFFFFFFFFu, mg, off));
            float e = __expf(mw - mg);                 // inactive lanes: 0
            float S = e * sw;
            #pragma unroll
            for (int off = 16; off > 0; off >>= 1)
                S += __shfl_xor_sync(0xFFFFFFFFu, S, off);
            if (lane < NWARP) s_fac[lane] = e / S;
        }
        __syncthreads();

        const float f = s_fac[warp];
        float4* stp = (float4*)(stage + warp * D_DIM);
        stp[lane +  0] = make_float4(acc0.x * f, acc0.y * f, acc0.z * f, acc0.w * f);
        stp[lane + 32] = make_float4(acc1.x * f, acc1.y * f, acc1.z * f, acc1.w * f);
        stp[lane + 64] = make_float4(acc2.x * f, acc2.y * f, acc2.z * f, acc2.w * f);
        stp[lane + 96] = make_float4(acc3.x * f, acc3.y * f, acc3.z * f, acc3.w * f);
        __syncthreads();

        float v0 = 0.0f, v1 = 0.0f;
        #pragma unroll
        for (int w = 0; w < NWARP; w++) {
            v0 += stage[w * D_DIM + tid];
            v1 += stage[w * D_DIM + tid + 256];
        }
        out[(size_t)b * D_DIM + tid]       = v0;
        out[(size_t)b * D_DIM + tid + 256] = v1;

        __syncthreads();   // protect stage/s_m/s_s before next tile reuses them
    }
}

extern "C" void kernel_launch(void* const* d_in, const int* in_sizes, int n_in,
                              void* d_out, int out_size) {
    const float* h     = (const float*)d_in[0];
    const float* keys  = (const float*)d_in[1];
    const int*   sigma = (const int*)d_in[2];
    float*       out   = (float*)d_out;

    cudaFuncSetAttribute(block_diag_agg_kernel,
                         cudaFuncAttributeMaxDynamicSharedMemorySize, SMEM_TOTAL);
    block_diag_agg_kernel<<<GRID, THREADS, SMEM_TOTAL>>>(h, keys, sigma, out);
}

// round 16
// speedup vs baseline: 1.1423x; 1.0483x over previous
#include <cuda_runtime.h>
#include <cstddef>
#include <cstdint>
#include <math_constants.h>

#define B_DIM 4096
#define K_DIM 64
#define D_DIM 512
#define N_AGENTS 64
#define NEG_INF -1e9f
#define THREADS 256
#define NWARP 8
#define GRID 444                              // 148 SMs x 3 resident CTAs
#define NBUF 4
#define CROWS 8
#define CBYTES (CROWS * D_DIM * 4)            // 16 KB
#define CFLOATS (CROWS * D_DIM)
#define HALF (D_DIM / 2)                      // 256
#define STAGE_OFF (NBUF * CBYTES)             // 65536
#define MBAR_OFF (STAGE_OFF + NWARP * HALF * 4)   // 65536 + 8192 = 73728
#define SMEM_TOTAL (MBAR_OFF + 64)

__device__ __forceinline__ uint32_t smem_u32(const void* p) {
    return (uint32_t)__cvta_generic_to_shared(p);
}
__device__ __forceinline__ void mbar_init(uint32_t a, uint32_t cnt) {
    asm volatile("mbarrier.init.shared.b64 [%0], %1;" :: "r"(a), "r"(cnt) : "memory");
}
__device__ __forceinline__ void mbar_expect_tx(uint32_t a, uint32_t bytes) {
    asm volatile("mbarrier.arrive.expect_tx.shared.b64 _, [%0], %1;" :: "r"(a), "r"(bytes) : "memory");
}
__device__ __forceinline__ void mbar_wait(uint32_t a, uint32_t parity) {
    while (true) {
        uint32_t done;
        asm volatile(
            "{\n\t.reg .pred p;\n\t"
            "mbarrier.try_wait.parity.acquire.cta.shared::cta.b64 p, [%1], %2, 0x989680;\n\t"
            "selp.b32 %0, 1, 0, p;\n\t}"
            : "=r"(done) : "r"(a), "r"(parity) : "memory");
        if (done) break;
    }
}
__device__ __forceinline__ void bulk_copy(uint32_t dst, const void* src, uint32_t bytes, uint32_t mbar) {
    asm volatile(
        "cp.async.bulk.shared::cluster.global.mbarrier::complete_tx::bytes [%0], [%1], %2, [%3];"
        :: "r"(dst), "l"(src), "r"(bytes), "r"(mbar) : "memory");
}

__global__ __launch_bounds__(THREADS, 3)
void block_diag_agg_kernel(const float* __restrict__ h,
                           const float* __restrict__ keys,
                           const int* __restrict__ sigma,
                           float* __restrict__ out) {
    extern __shared__ __align__(128) char smem[];
    __shared__ float s_m[NWARP];
    __shared__ float s_s[NWARP];
    __shared__ float s_fac[NWARP];

    const int tid  = threadIdx.x;
    const int warp = tid >> 5;
    const int lane = tid & 31;
    const int bid  = blockIdx.x;

    const uint32_t sb32     = smem_u32(smem);
    const uint32_t full_bar = sb32 + MBAR_OFF;    // 4 x 8 B

    const int ntiles = (B_DIM - bid + GRID - 1) / GRID;   // 9 or 10
    const int total  = ntiles * 8;

    if (tid == 0) {
        #pragma unroll
        for (int s = 0; s < NBUF; s++) mbar_init(full_bar + s * 8, 1);
    }
    __syncthreads();

    // ---- Prologue: queue the first NBUF chunks (tile 0) ----
    if (tid == 0) {
        #pragma unroll
        for (int g = 0; g < NBUF; g++) {
            const float* src = h + (size_t)bid * (K_DIM * D_DIM) + g * CFLOATS;
            mbar_expect_tx(full_bar + g * 8, CBYTES);
            bulk_copy(sb32 + g * CBYTES, src, CBYTES, full_bar + g * 8);
        }
    }

    float* stage = (float*)(smem + STAGE_OFF);    // [NWARP][256]

    for (int t = 0; t < ntiles; t++) {
        const int b   = bid + t * GRID;
        const int* sg = sigma + (size_t)b * K_DIM;

        float m = -CUDART_INF_F;
        float s = 0.0f;
        float4 acc0 = make_float4(0.f, 0.f, 0.f, 0.f);
        float4 acc1 = make_float4(0.f, 0.f, 0.f, 0.f);
        float4 acc2 = make_float4(0.f, 0.f, 0.f, 0.f);
        float4 acc3 = make_float4(0.f, 0.f, 0.f, 0.f);

        #pragma unroll
        for (int c = 0; c < 8; c++) {
            // NBUF=4, 8 chunks/tile: slot and parity are compile-time per c
            const int buf = c & 3;
            mbar_wait(full_bar + buf * 8, (c >> 2) & 1 ^ 0);  // parity = (g>>2)&1, g=t*8+c -> (2t + (c>>2))&1 = (c>>2)&1
            // NOTE: (t*8+c)>>2 = 2t + (c>>2); &1 kills the 2t term.

            const int k = c * CROWS + warp;       // warp w consumes row w
            const int sid    = __ldg(&sg[k]);
            const bool valid = (sid < N_AGENTS);
            const float4* hrow = (const float4*)(smem + buf * CBYTES + warp * (D_DIM * 4));
            const float4* krow = (const float4*)(keys + (size_t)(valid ? sid : 0) * D_DIM);

            float4 hv0 = hrow[lane +  0];
            float4 hv1 = hrow[lane + 32];
            float4 hv2 = hrow[lane + 64];
            float4 hv3 = hrow[lane + 96];
            float4 kv0 = __ldg(&krow[lane +  0]);
            float4 kv1 = __ldg(&krow[lane + 32]);
            float4 kv2 = __ldg(&krow[lane + 64]);
            float4 kv3 = __ldg(&krow[lane + 96]);

            float dot = 0.0f;
            dot = fmaf(hv0.x, kv0.x, dot); dot = fmaf(hv0.y, kv0.y, dot);
            dot = fmaf(hv0.z, kv0.z, dot); dot = fmaf(hv0.w, kv0.w, dot);
            dot = fmaf(hv1.x, kv1.x, dot); dot = fmaf(hv1.y, kv1.y, dot);
            dot = fmaf(hv1.z, kv1.z, dot); dot = fmaf(hv1.w, kv1.w, dot);
            dot = fmaf(hv2.x, kv2.x, dot); dot = fmaf(hv2.y, kv2.y, dot);
            dot = fmaf(hv2.z, kv2.z, dot); dot = fmaf(hv2.w, kv2.w, dot);
            dot = fmaf(hv3.x, kv3.x, dot); dot = fmaf(hv3.y, kv3.y, dot);
            dot = fmaf(hv3.z, kv3.z, dot); dot = fmaf(hv3.w, kv3.w, dot);

            #pragma unroll
            for (int off = 16; off > 0; off >>= 1)
                dot += __shfl_xor_sync(0xFFFFFFFFu, dot, off);

            const float logit = valid ? dot : NEG_INF;
            const float m_new = fmaxf(m, logit);
            const float scale = __expf(m - m_new);     // iter 0: exp(-inf)=0
            const float pw    = __expf(logit - m_new);
            s = fmaf(s, scale, pw);
            m = m_new;

            acc0.x = fmaf(acc0.x, scale, pw * hv0.x);
            acc0.y = fmaf(acc0.y, scale, pw * hv0.y);
            acc0.z = fmaf(acc0.z, scale, pw * hv0.z);
            acc0.w = fmaf(acc0.w, scale, pw * hv0.w);
            acc1.x = fmaf(acc1.x, scale, pw * hv1.x);
            acc1.y = fmaf(acc1.y, scale, pw * hv1.y);
            acc1.z = fmaf(acc1.z, scale, pw * hv1.z);
            acc1.w = fmaf(acc1.w, scale, pw * hv1.w);
            acc2.x = fmaf(acc2.x, scale, pw * hv2.x);
            acc2.y = fmaf(acc2.y, scale, pw * hv2.y);
            acc2.z = fmaf(acc2.z, scale, pw * hv2.z);
            acc2.w = fmaf(acc2.w, scale, pw * hv2.w);
            acc3.x = fmaf(acc3.x, scale, pw * hv3.x);
            acc3.y = fmaf(acc3.y, scale, pw * hv3.y);
            acc3.z = fmaf(acc3.z, scale, pw * hv3.z);
            acc3.w = fmaf(acc3.w, scale, pw * hv3.w);

            __syncthreads();   // all warps done with this buffer

            if (tid == 0) {
                const int g = t * 8 + c;
                if (g + NBUF < total) {
                    const int gn = g + NBUF, tn = gn >> 3, cn = gn & 7;
                    const float* src = h + (size_t)(bid + tn * GRID) * (K_DIM * D_DIM) + cn * CFLOATS;
                    mbar_expect_tx(full_bar + buf * 8, CBYTES);
                    bulk_copy(sb32 + buf * CBYTES, src, CBYTES, full_bar + buf * 8);
                }
            }
        }

        // ---- Epilogue: merge softmax states, then reduce in 2 half-rows ----
        if (lane == 0) { s_m[warp] = m; s_s[warp] = s; }
        __syncthreads();

        if (warp == 0) {
            float mw = (lane < NWARP) ? s_m[lane] : -CUDART_INF_F;
            float sw = (lane < NWARP) ? s_s[lane] : 0.0f;
            float mg = mw;
            #pragma unroll
            for (int off = 16; off > 0; off >>= 1)
                mg = fmaxf(mg, __shfl_xor_sync(0xFFFFFFFFu, mg, off));
            float e = __expf(mw - mg);                 // inactive lanes: 0
            float S = e * sw;
            #pragma unroll
            for (int off = 16; off > 0; off >>= 1)
                S += __shfl_xor_sync(0xFFFFFFFFu, S, off);
            if (lane < NWARP) s_fac[lane] = e / S;
        }
        __syncthreads();

        const float f = s_fac[warp];
        float4* stp = (float4*)(stage + warp * HALF);

        // Round A: dims 0..255 (acc0, acc1)
        stp[lane +  0] = make_float4(acc0.x * f, acc0.y * f, acc0.z * f, acc0.w * f);
        stp[lane + 32] = make_float4(acc1.x * f, acc1.y * f, acc1.z * f, acc1.w * f);
        __syncthreads();
        {
            float v = 0.0f;
            #pragma unroll
            for (int w = 0; w < NWARP; w++) v += stage[w * HALF + tid];
            out[(size_t)b * D_DIM + tid] = v;
        }
        __syncthreads();

        // Round B: dims 256..511 (acc2, acc3)
        stp[lane +  0] = make_float4(acc2.x * f, acc2.y * f, acc2.z * f, acc2.w * f);
        stp[lane + 32] = make_float4(acc3.x * f, acc3.y * f, acc3.z * f, acc3.w * f);
        __syncthreads();
        {
            float v = 0.0f;
            #pragma unroll
            for (int w = 0; w < NWARP; w++) v += stage[w * HALF + tid];
            out[(size_t)b * D_DIM + HALF + tid] = v;
        }
        __syncthreads();   // protect stage/s_m/s_s before next tile
    }
}

extern "C" void kernel_launch(void* const* d_in, const int* in_sizes, int n_in,
                              void* d_out, int out_size) {
    const float* h     = (const float*)d_in[0];
    const float* keys  = (const float*)d_in[1];
    const int*   sigma = (const int*)d_in[2];
    float*       out   = (float*)d_out;

    cudaFuncSetAttribute(block_diag_agg_kernel,
                         cudaFuncAttributeMaxDynamicSharedMemorySize, SMEM_TOTAL);
    block_diag_agg_kernel<<<GRID, THREADS, SMEM_TOTAL>>>(h, keys, sigma, out);
}

// round 17
// speedup vs baseline: 1.2012x; 1.0516x over previous
#include <cuda_runtime.h>
#include <cuda_fp16.h>
#include <cstddef>
#include <cstdint>
#include <math_constants.h>

#define B_DIM 4096
#define K_DIM 64
#define D_DIM 512
#define N_AGENTS 64
#define NEG_INF -1e9f
#define THREADS 256
#define NWARP 8
#define GRID 444                              // 148 SMs x 3 resident CTAs
#define NBUF 4
#define CROWS 8
#define CBYTES (CROWS * D_DIM * 4)            // 16 KB
#define CFLOATS (CROWS * D_DIM)
#define HALF 256
#define STAGE_OFF (NBUF * CBYTES)             // 65536
#define MBAR_OFF (STAGE_OFF + NWARP * HALF * 4)   // 73728
#define SMEM_TOTAL (MBAR_OFF + 64)

// fp16 keys, lane-permuted: row sid, lane l holds halfs for
// d = 4l..4l+3, 4(l+32).., 4(l+64).., 4(l+96).. at offset sid*512 + l*16
__device__ __align__(16) __half g_keys_packed[N_AGENTS * D_DIM];

__global__ void pack_keys_kernel(const float* __restrict__ keys) {
    const int sid  = blockIdx.x;      // 0..63
    const int lane = threadIdx.x;     // 0..31
    const float* row = keys + (size_t)sid * D_DIM;
    __half* dst = g_keys_packed + (size_t)sid * D_DIM + lane * 16;
    #pragma unroll
    for (int gp = 0; gp < 4; gp++) {
        const int d0 = 4 * (lane + 32 * gp);
        #pragma unroll
        for (int j = 0; j < 4; j++)
            dst[gp * 4 + j] = __float2half(row[d0 + j]);
    }
}

__device__ __forceinline__ uint32_t smem_u32(const void* p) {
    return (uint32_t)__cvta_generic_to_shared(p);
}
__device__ __forceinline__ void mbar_init(uint32_t a, uint32_t cnt) {
    asm volatile("mbarrier.init.shared.b64 [%0], %1;" :: "r"(a), "r"(cnt) : "memory");
}
__device__ __forceinline__ void mbar_expect_tx(uint32_t a, uint32_t bytes) {
    asm volatile("mbarrier.arrive.expect_tx.shared.b64 _, [%0], %1;" :: "r"(a), "r"(bytes) : "memory");
}
__device__ __forceinline__ void mbar_wait(uint32_t a, uint32_t parity) {
    while (true) {
        uint32_t done;
        asm volatile(
            "{\n\t.reg .pred p;\n\t"
            "mbarrier.try_wait.parity.acquire.cta.shared::cta.b64 p, [%1], %2, 0x989680;\n\t"
            "selp.b32 %0, 1, 0, p;\n\t}"
            : "=r"(done) : "r"(a), "r"(parity) : "memory");
        if (done) break;
    }
}
__device__ __forceinline__ void bulk_copy(uint32_t dst, const void* src, uint32_t bytes, uint32_t mbar) {
    asm volatile(
        "cp.async.bulk.shared::cluster.global.mbarrier::complete_tx::bytes [%0], [%1], %2, [%3];"
        :: "r"(dst), "l"(src), "r"(bytes), "r"(mbar) : "memory");
}
#define H2F(u) __half22float2(*reinterpret_cast<const __half2*>(&(u)))

__global__ __launch_bounds__(THREADS, 3)
void block_diag_agg_kernel(const float* __restrict__ h,
                           const int* __restrict__ sigma,
                           float* __restrict__ out) {
    extern __shared__ __align__(128) char smem[];
    __shared__ float s_m[NWARP];
    __shared__ float s_s[NWARP];
    __shared__ float s_fac[NWARP];

    const int tid  = threadIdx.x;
    const int warp = tid >> 5;
    const int lane = tid & 31;
    const int bid  = blockIdx.x;

    const uint32_t sb32     = smem_u32(smem);
    const uint32_t full_bar = sb32 + MBAR_OFF;    // 4 x 8 B

    const int ntiles = (B_DIM - bid + GRID - 1) / GRID;
    const int total  = ntiles * 8;

    if (tid == 0) {
        #pragma unroll
        for (int s = 0; s < NBUF; s++) mbar_init(full_bar + s * 8, 1);
    }
    __syncthreads();

    if (tid == 0) {
        #pragma unroll
        for (int g = 0; g < NBUF; g++) {
            const float* src = h + (size_t)bid * (K_DIM * D_DIM) + g * CFLOATS;
            mbar_expect_tx(full_bar + g * 8, CBYTES);
            bulk_copy(sb32 + g * CBYTES, src, CBYTES, full_bar + g * 8);
        }
    }

    float* stage = (float*)(smem + STAGE_OFF);    // [NWARP][256]
    const uint4* kpk = (const uint4*)g_keys_packed;

    for (int t = 0; t < ntiles; t++) {
        const int b   = bid + t * GRID;
        const int* sg = sigma + (size_t)b * K_DIM;

        // preload this warp's 8 sids for the tile
        int sids[8];
        #pragma unroll
        for (int c = 0; c < 8; c++) sids[c] = __ldg(&sg[c * CROWS + warp]);

        float m = -CUDART_INF_F;
        float s = 0.0f;
        float4 acc0 = make_float4(0.f, 0.f, 0.f, 0.f);
        float4 acc1 = make_float4(0.f, 0.f, 0.f, 0.f);
        float4 acc2 = make_float4(0.f, 0.f, 0.f, 0.f);
        float4 acc3 = make_float4(0.f, 0.f, 0.f, 0.f);

        // kv pipeline: preload chunk 0's key row
        uint4 kvA_n, kvB_n;
        {
            const int i0 = (sids[0] < N_AGENTS) ? sids[0] : 0;
            const uint4* kp = kpk + (size_t)i0 * 64 + lane * 2;
            kvA_n = __ldg(kp);
            kvB_n = __ldg(kp + 1);
        }

        #pragma unroll
        for (int c = 0; c < 8; c++) {
            const uint4 kvA = kvA_n;
            const uint4 kvB = kvB_n;
            if (c < 7) {        // issue next chunk's kv before waiting: hides L2 latency
                const int in = (sids[c + 1] < N_AGENTS) ? sids[c + 1] : 0;
                const uint4* kp = kpk + (size_t)in * 64 + lane * 2;
                kvA_n = __ldg(kp);
                kvB_n = __ldg(kp + 1);
            }

            const int buf = c & 3;                     // compile-time slot
            mbar_wait(full_bar + buf * 8, (c >> 2) & 1);  // parity: (t*8+c)>>2 = 2t+(c>>2); &1 kills 2t

            const bool valid = (sids[c] < N_AGENTS);
            const float4* hrow = (const float4*)(smem + buf * CBYTES + warp * (D_DIM * 4));

            float4 hv0 = hrow[lane +  0];
            float4 hv1 = hrow[lane + 32];
            float4 hv2 = hrow[lane + 64];
            float4 hv3 = hrow[lane + 96];

            float dot = 0.0f;
            float2 f;
            f = H2F(kvA.x); dot = fmaf(hv0.x, f.x, dot); dot = fmaf(hv0.y, f.y, dot);
            f = H2F(kvA.y); dot = fmaf(hv0.z, f.x, dot); dot = fmaf(hv0.w, f.y, dot);
            f = H2F(kvA.z); dot = fmaf(hv1.x, f.x, dot); dot = fmaf(hv1.y, f.y, dot);
            f = H2F(kvA.w); dot = fmaf(hv1.z, f.x, dot); dot = fmaf(hv1.w, f.y, dot);
            f = H2F(kvB.x); dot = fmaf(hv2.x, f.x, dot); dot = fmaf(hv2.y, f.y, dot);
            f = H2F(kvB.y); dot = fmaf(hv2.z, f.x, dot); dot = fmaf(hv2.w, f.y, dot);
            f = H2F(kvB.z); dot = fmaf(hv3.x, f.x, dot); dot = fmaf(hv3.y, f.y, dot);
            f = H2F(kvB.w); dot = fmaf(hv3.z, f.x, dot); dot = fmaf(hv3.w, f.y, dot);

            #pragma unroll
            for (int off = 16; off > 0; off >>= 1)
                dot += __shfl_xor_sync(0xFFFFFFFFu, dot, off);

            const float logit = valid ? dot : NEG_INF;
            const float m_new = fmaxf(m, logit);
            const float scale = __expf(m - m_new);     // iter 0: exp(-inf)=0
            const float pw    = __expf(logit - m_new);
            s = fmaf(s, scale, pw);
            m = m_new;

            acc0.x = fmaf(acc0.x, scale, pw * hv0.x);
            acc0.y = fmaf(acc0.y, scale, pw * hv0.y);
            acc0.z = fmaf(acc0.z, scale, pw * hv0.z);
            acc0.w = fmaf(acc0.w, scale, pw * hv0.w);
            acc1.x = fmaf(acc1.x, scale, pw * hv1.x);
            acc1.y = fmaf(acc1.y, scale, pw * hv1.y);
            acc1.z = fmaf(acc1.z, scale, pw * hv1.z);
            acc1.w = fmaf(acc1.w, scale, pw * hv1.w);
            acc2.x = fmaf(acc2.x, scale, pw * hv2.x);
            acc2.y = fmaf(acc2.y, scale, pw * hv2.y);
            acc2.z = fmaf(acc2.z, scale, pw * hv2.z);
            acc2.w = fmaf(acc2.w, scale, pw * hv2.w);
            acc3.x = fmaf(acc3.x, scale, pw * hv3.x);
            acc3.y = fmaf(acc3.y, scale, pw * hv3.y);
            acc3.z = fmaf(acc3.z, scale, pw * hv3.z);
            acc3.w = fmaf(acc3.w, scale, pw * hv3.w);

            __syncthreads();   // all warps done with this buffer

            if (tid == 0) {
                const int g = t * 8 + c;
                if (g + NBUF < total) {
                    const int gn = g + NBUF, tn = gn >> 3, cn = gn & 7;
                    const float* src = h + (size_t)(bid + tn * GRID) * (K_DIM * D_DIM) + cn * CFLOATS;
                    mbar_expect_tx(full_bar + buf * 8, CBYTES);
                    bulk_copy(sb32 + buf * CBYTES, src, CBYTES, full_bar + buf * 8);
                }
            }
        }

        // ---- Epilogue: merge softmax states, then reduce in 2 half-rows ----
        if (lane == 0) { s_m[warp] = m; s_s[warp] = s; }
        __syncthreads();

        if (warp == 0) {
            float mw = (lane < NWARP) ? s_m[lane] : -CUDART_INF_F;
            float sw = (lane < NWARP) ? s_s[lane] : 0.0f;
            float mg = mw;
            #pragma unroll
            for (int off = 16; off > 0; off >>= 1)
                mg = fmaxf(mg, __shfl_xor_sync(0xFFFFFFFFu, mg, off));
            float e = __expf(mw - mg);                 // inactive lanes: 0
            float S = e * sw;
            #pragma unroll
            for (int off = 16; off > 0; off >>= 1)
                S += __shfl_xor_sync(0xFFFFFFFFu, S, off);
            if (lane < NWARP) s_fac[lane] = e / S;
        }
        __syncthreads();

        const float f = s_fac[warp];
        float4* stp = (float4*)(stage + warp * HALF);

        // Round A: dims 0..255 (acc0, acc1)
        stp[lane +  0] = make_float4(acc0.x * f, acc0.y * f, acc0.z * f, acc0.w * f);
        stp[lane + 32] = make_float4(acc1.x * f, acc1.y * f, acc1.z * f, acc1.w * f);
        __syncthreads();
        {
            float v = 0.0f;
            #pragma unroll
            for (int w = 0; w < NWARP; w++) v += stage[w * HALF + tid];
            out[(size_t)b * D_DIM + tid] = v;
        }
        __syncthreads();

        // Round B: dims 256..511 (acc2, acc3)
        stp[lane +  0] = make_float4(acc2.x * f, acc2.y * f, acc2.z * f, acc2.w * f);
        stp[lane + 32] = make_float4(acc3.x * f, acc3.y * f, acc3.z * f, acc3.w * f);
        __syncthreads();
        {
            float v = 0.0f;
            #pragma unroll
            for (int w = 0; w < NWARP; w++) v += stage[w * HALF + tid];
            out[(size_t)b * D_DIM + HALF + tid] = v;
        }
        __syncthreads();   // protect stage/s_m/s_s before next tile
    }
}

extern "C" void kernel_launch(void* const* d_in, const int* in_sizes, int n_in,
                              void* d_out, int out_size) {
    const float* h     = (const float*)d_in[0];
    const float* keys  = (const float*)d_in[1];
    const int*   sigma = (const int*)d_in[2];
    float*       out   = (float*)d_out;

    pack_keys_kernel<<<N_AGENTS, 32>>>(keys);

    cudaFuncSetAttribute(block_diag_agg_kernel,
                         cudaFuncAttributeMaxDynamicSharedMemorySize, SMEM_TOTAL);
    block_diag_agg_kernel<<<GRID, THREADS, SMEM_TOTAL>>>(h, sigma, out);
}